// round 7
// baseline (speedup 1.0000x reference)
#include <cuda_runtime.h>
#include <cuda_bf16.h>
#include <cstdint>

#define Cdim 256
#define Ldim 4096
#define Nb   64
#define MTOT (Nb * Ldim)

// ---------------- static device scratch ----------------
__device__ float g_part[3][128][128 * 128];   // gram partials (tile, n*2+kh)
__device__ float g_msum[128 * 256];           // row-sum partials
__device__ float g_mean[Cdim];
__device__ float g_sigma[Cdim * Cdim];
__device__ float g_scal[4];
__device__ float g_NS[5][Cdim * Cdim];        // 0:E0 1:E2 2:Bmat/Zn 3:amat 4:G
__device__ __nv_bfloat16 g_Ebf[Cdim * Cdim];  // E = scal1*Zn - I in bf16
__device__ float g_b[Cdim];

// ---------------- PTX helpers (plain sm_80+ features only) ----------------
__device__ __forceinline__ uint32_t smem_u32(const void* p) {
    uint32_t a;
    asm("{ .reg .u64 t; cvta.to.shared.u64 t, %1; cvt.u32.u64 %0, t; }" : "=r"(a) : "l"(p));
    return a;
}
__device__ __forceinline__ void mma16816(float* d, const uint32_t* a, const uint32_t* b) {
    asm volatile(
        "mma.sync.aligned.m16n8k16.row.col.f32.bf16.bf16.f32 "
        "{%0,%1,%2,%3}, {%4,%5,%6,%7}, {%8,%9}, {%0,%1,%2,%3};"
        : "+f"(d[0]), "+f"(d[1]), "+f"(d[2]), "+f"(d[3])
        : "r"(a[0]), "r"(a[1]), "r"(a[2]), "r"(a[3]), "r"(b[0]), "r"(b[1]));
}
__device__ __forceinline__ void ldsm4(uint32_t* r, uint32_t addr) {
    asm volatile("ldmatrix.sync.aligned.m8n8.x4.shared.b16 {%0,%1,%2,%3}, [%4];"
                 : "=r"(r[0]), "=r"(r[1]), "=r"(r[2]), "=r"(r[3]) : "r"(addr));
}
__device__ __forceinline__ void ldsm2(uint32_t* r, uint32_t addr) {
    asm volatile("ldmatrix.sync.aligned.m8n8.x2.shared.b16 {%0,%1}, [%2];"
                 : "=r"(r[0]), "=r"(r[1]) : "r"(addr));
}
__device__ __forceinline__ void ldsm2t(uint32_t* r, uint32_t addr) {
    asm volatile("ldmatrix.sync.aligned.m8n8.x2.trans.shared.b16 {%0,%1}, [%2];"
                 : "=r"(r[0]), "=r"(r[1]) : "r"(addr));
}
__device__ __forceinline__ void cpasync16(uint32_t smem, const void* g) {
    asm volatile("cp.async.cg.shared.global [%0], [%1], 16;" :: "r"(smem), "l"(g));
}
__device__ __forceinline__ void cpcommit() { asm volatile("cp.async.commit_group;" ::: "memory"); }
template <int N>
__device__ __forceinline__ void cpwait() {
    asm volatile("cp.async.wait_group %0;" :: "n"(N) : "memory");
}
__device__ __forceinline__ uint4 pack_bf16(const float4& a, const float4& b) {
    uint4 o;
    __nv_bfloat162 h;
    h = __floats2bfloat162_rn(a.x, a.y); o.x = *(uint32_t*)&h;
    h = __floats2bfloat162_rn(a.z, a.w); o.y = *(uint32_t*)&h;
    h = __floats2bfloat162_rn(b.x, b.y); o.z = *(uint32_t*)&h;
    h = __floats2bfloat162_rn(b.z, b.w); o.w = *(uint32_t*)&h;
    return o;
}

// ---------------- 1) Gram: fp32 X -> bf16 smem on the fly, fused mean partials ----------------
#define GP 144  // 64 bf16 = 128B + 16 pad
__global__ __launch_bounds__(256) void gram_kernel(const float* __restrict__ X) {
    extern __shared__ __align__(128) char sm[];
    const uint32_t sb = smem_u32(sm);
    const int t = threadIdx.x;
    const int warp = t >> 5, lane = t & 31;
    const int wm = warp >> 2, wn = warp & 3;  // 2x4 warp grid, warp tile 64x32
    const int tile = blockIdx.x, n = blockIdx.y, kh = blockIdx.z;
    const int ti = (tile == 0) ? 0 : 1;
    const int tj = (tile == 2) ? 1 : 0;
    const bool diag = (tile != 1);
    const uint32_t oA[2] = {sb, sb + 36864};
    const uint32_t oB[2] = {sb + 18432, sb + 55296};
    const uint32_t offA[2] = {0u, 36864u};
    const uint32_t offB[2] = {18432u, 55296u};

    const int lrow = t >> 1, lhalf = t & 1;
    const float4* AV = (const float4*)(X + (size_t)(n * 256 + ti * 128 + lrow) * Ldim + kh * 2048);
    const float4* BV = (const float4*)(X + (size_t)(n * 256 + tj * 128 + lrow) * Ldim + kh * 2048);

    float4 ra[8], rb[8];
    float sumA = 0.0f, sumB = 0.0f;

    auto loadregs = [&](int s) {
        const int base = s * 16 + lhalf * 8;
#pragma unroll
        for (int i = 0; i < 8; ++i) ra[i] = AV[base + i];
        if (!diag) {
#pragma unroll
            for (int i = 0; i < 8; ++i) rb[i] = BV[base + i];
#pragma unroll
            for (int i = 0; i < 8; ++i) {
                sumA += ra[i].x + ra[i].y + ra[i].z + ra[i].w;
                sumB += rb[i].x + rb[i].y + rb[i].z + rb[i].w;
            }
        }
    };
    auto stsbuf = [&](int b) {
        char* pa = sm + offA[b] + lrow * GP + lhalf * 64;
#pragma unroll
        for (int j = 0; j < 4; ++j)
            *(uint4*)(pa + j * 16) = pack_bf16(ra[2 * j], ra[2 * j + 1]);
        if (!diag) {
            char* pb = sm + offB[b] + lrow * GP + lhalf * 64;
#pragma unroll
            for (int j = 0; j < 4; ++j)
                *(uint4*)(pb + j * 16) = pack_bf16(rb[2 * j], rb[2 * j + 1]);
        }
    };

    float acc[4][4][4];
#pragma unroll
    for (int i = 0; i < 4; ++i)
#pragma unroll
        for (int j = 0; j < 4; ++j)
#pragma unroll
            for (int r = 0; r < 4; ++r) acc[i][j][r] = 0.0f;

    loadregs(0);
    stsbuf(0);

    for (int s = 0; s < 32; ++s) {
        __syncthreads();
        if (s < 31) loadregs(s + 1);
        const uint32_t sa = oA[s & 1];
        const uint32_t sbuf = diag ? sa : oB[s & 1];
#pragma unroll
        for (int ks = 0; ks < 4; ++ks) {
            uint32_t af[4][4], bf[4][2];
#pragma unroll
            for (int mi = 0; mi < 4; ++mi)
                ldsm4(af[mi], sa + (wm * 64 + mi * 16 + (lane & 15)) * GP +
                                  ks * 32 + ((lane >> 4) * 16));
#pragma unroll
            for (int ni = 0; ni < 4; ++ni)
                ldsm2(bf[ni], sbuf + (wn * 32 + ni * 8 + (lane & 7)) * GP +
                                  ks * 32 + (((lane >> 3) & 1) * 16));
#pragma unroll
            for (int mi = 0; mi < 4; ++mi)
#pragma unroll
                for (int ni = 0; ni < 4; ++ni)
                    mma16816(acc[mi][ni], af[mi], bf[ni]);
        }
        if (s < 31) stsbuf((s + 1) & 1);
    }
    __syncthreads();

    float* outp = g_part[tile][n * 2 + kh];
#pragma unroll
    for (int mi = 0; mi < 4; ++mi)
#pragma unroll
        for (int ni = 0; ni < 4; ++ni) {
            int r0 = wm * 64 + mi * 16 + (lane >> 2);
            int c0 = wn * 32 + ni * 8 + (lane & 3) * 2;
            *(float2*)(outp + r0 * 128 + c0)       = make_float2(acc[mi][ni][0], acc[mi][ni][1]);
            *(float2*)(outp + (r0 + 8) * 128 + c0) = make_float2(acc[mi][ni][2], acc[mi][ni][3]);
        }

    if (!diag) {
        float* red = (float*)sm;
        red[t] = sumA;
        red[256 + t] = sumB;
        __syncthreads();
        if (t < 128) {
            // A slab = rows 128..255, B slab = rows 0..127 (row = 2 threads each)
            g_msum[(n * 2 + kh) * 256 + 128 + t] = red[2 * t] + red[2 * t + 1];
            g_msum[(n * 2 + kh) * 256 + t]       = red[256 + 2 * t] + red[256 + 2 * t + 1];
        }
    }
}

__global__ void mean_reduce() {
    const int c = threadIdx.x;
    float s = 0.0f;
    for (int p = 0; p < 128; ++p) s += g_msum[p * 256 + c];
    g_mean[c] = s * (1.0f / (float)MTOT);
}

// ---------------- 2) sigma assembly (deterministic reduce over 128 splits) ----------------
__global__ void sigma_kernel() {
    const int idx = blockIdx.x * 256 + threadIdx.x;
    const int i = idx >> 8, j = idx & 255;
    int tile, ii, jj;
    if (i < 128 && j < 128)        { tile = 0; ii = i;       jj = j; }
    else if (i >= 128 && j < 128)  { tile = 1; ii = i - 128; jj = j; }
    else if (i >= 128 && j >= 128) { tile = 2; ii = i - 128; jj = j - 128; }
    else                           { tile = 1; ii = j - 128; jj = i; }  // symmetry
    float s = 0.0f;
#pragma unroll 16
    for (int p = 0; p < 128; ++p) s += g_part[tile][p][ii * 128 + jj];
    float v = s * (1.0f / (float)MTOT) - g_mean[i] * g_mean[j];
    if (i == j) v += 1e-3f;
    g_sigma[idx] = v;
}

__global__ void trace_kernel() {
    __shared__ float red[256];
    const int t = threadIdx.x;
    red[t] = g_sigma[t * 257];
    __syncthreads();
    for (int o = 128; o > 0; o >>= 1) {
        if (t < o) red[t] += red[t + o];
        __syncthreads();
    }
    if (t == 0) {
        float s = red[0] * (1.0f / 256.0f);
        g_scal[0] = 1.0f / s;
        g_scal[1] = rsqrtf(s);
    }
}

__global__ void e0_kernel() {  // E0 = sigma/s - I
    const int idx = blockIdx.x * 256 + threadIdx.x;
    g_NS[0][idx] = g_sigma[idx] * g_scal[0] - (((idx >> 8) == (idx & 255)) ? 1.0f : 0.0f);
}

// ---------------- 3) fp32 256^3 GEMM core for polynomial inverse-sqrt ----------------
__device__ __forceinline__ void ns_core(const float* A, const float* B, float acc[4][4]) {
    const int ti = blockIdx.x >> 2, tj = blockIdx.x & 3;
    __shared__ float As[64][17];
    __shared__ float Bs[16][68];
    const int t = threadIdx.x;
    const int tx = t & 15, ty = t >> 4;
    for (int k0 = 0; k0 < 256; k0 += 16) {
        float4 av = *(const float4*)(A + (size_t)(ti * 64 + (t >> 2)) * 256 + k0 + ((t & 3) << 2));
        float4 bv = *(const float4*)(B + (size_t)(k0 + (t >> 4)) * 256 + tj * 64 + ((t & 15) << 2));
        __syncthreads();
        {
            const int ar = t >> 2, ak = (t & 3) << 2;
            As[ar][ak + 0] = av.x; As[ar][ak + 1] = av.y; As[ar][ak + 2] = av.z; As[ar][ak + 3] = av.w;
            *(float4*)&Bs[t >> 4][(t & 15) << 2] = bv;
        }
        __syncthreads();
#pragma unroll
        for (int k = 0; k < 16; ++k) {
            float4 b = *(const float4*)&Bs[k][tx << 2];
            float a0 = As[ty * 4 + 0][k], a1 = As[ty * 4 + 1][k];
            float a2 = As[ty * 4 + 2][k], a3 = As[ty * 4 + 3][k];
            acc[0][0] += a0 * b.x; acc[0][1] += a0 * b.y; acc[0][2] += a0 * b.z; acc[0][3] += a0 * b.w;
            acc[1][0] += a1 * b.x; acc[1][1] += a1 * b.y; acc[1][2] += a1 * b.z; acc[1][3] += a1 * b.w;
            acc[2][0] += a2 * b.x; acc[2][1] += a2 * b.y; acc[2][2] += a2 * b.z; acc[2][3] += a2 * b.w;
            acc[3][0] += a3 * b.x; acc[3][1] += a3 * b.y; acc[3][2] += a3 * b.z; acc[3][3] += a3 * b.w;
        }
    }
}

// Taylor of (1+x)^{-1/2}: 1, -1/2, 3/8, -5/16, 35/128, -63/256
__global__ void poly1() {  // E2 = E0@E0; amat = c0 I + c1 E0 + c2 E2; Bmat = c3 I + c4 E0 + c5 E2
    float acc[4][4] = {};
    ns_core(g_NS[0], g_NS[0], acc);
    const int ti = blockIdx.x >> 2, tj = blockIdx.x & 3;
    const int t = threadIdx.x, tx = t & 15, ty = t >> 4;
#pragma unroll
    for (int i = 0; i < 4; ++i)
#pragma unroll
        for (int j = 0; j < 4; ++j) {
            const int gi = ti * 64 + ty * 4 + i, gj = tj * 64 + tx * 4 + j;
            const float d = (gi == gj) ? 1.0f : 0.0f;
            const float e0 = g_NS[0][gi * 256 + gj];
            const float e2 = acc[i][j];
            g_NS[1][gi * 256 + gj] = e2;
            g_NS[3][gi * 256 + gj] = d - 0.5f * e0 + 0.375f * e2;
            g_NS[2][gi * 256 + gj] = -0.3125f * d + 0.2734375f * e0 - 0.24609375f * e2;
        }
}
__global__ void poly2() {  // G = E2 @ Bmat
    float acc[4][4] = {};
    ns_core(g_NS[1], g_NS[2], acc);
    const int ti = blockIdx.x >> 2, tj = blockIdx.x & 3;
    const int t = threadIdx.x, tx = t & 15, ty = t >> 4;
#pragma unroll
    for (int i = 0; i < 4; ++i)
#pragma unroll
        for (int j = 0; j < 4; ++j)
            g_NS[4][(ti * 64 + ty * 4 + i) * 256 + tj * 64 + tx * 4 + j] = acc[i][j];
}
__global__ void poly3() {  // Zn = E0 @ G + amat  -> g_NS[2]
    float acc[4][4] = {};
    ns_core(g_NS[0], g_NS[4], acc);
    const int ti = blockIdx.x >> 2, tj = blockIdx.x & 3;
    const int t = threadIdx.x, tx = t & 15, ty = t >> 4;
#pragma unroll
    for (int i = 0; i < 4; ++i)
#pragma unroll
        for (int j = 0; j < 4; ++j) {
            const int gi = ti * 64 + ty * 4 + i, gj = tj * 64 + tx * 4 + j;
            g_NS[2][gi * 256 + gj] = acc[i][j] + g_NS[3][gi * 256 + gj];
        }
}

// ---------------- 4) E = scal1*Zn - I (bf16) and b = mu + E mu ----------------
__global__ void bE_kernel() {
    const int c = blockIdx.x, t = threadIdx.x;
    const float sc = g_scal[1];
    float e = sc * g_NS[2][c * 256 + t] - ((c == t) ? 1.0f : 0.0f);
    g_Ebf[c * 256 + t] = __float2bfloat16(e);
    __shared__ float red[256];
    red[t] = e * g_mean[t];
    __syncthreads();
    for (int o = 128; o > 0; o >>= 1) {
        if (t < o) red[t] += red[t + o];
        __syncthreads();
    }
    if (t == 0) g_b[c] = g_mean[c] + red[0];
}

// ---------------- 5) whiten: out = x - b + E @ x  (x -> bf16 in-kernel) ----------------
#define WPA 144  // E chunk pitch
#define WPB 272  // x chunk pitch: 128 bf16 = 256B + 16
__global__ __launch_bounds__(256, 2) void whiten_kernel(const float* __restrict__ X,
                                                        float* __restrict__ out) {
    extern __shared__ __align__(128) char sm[];
    const uint32_t sb = smem_u32(sm);
    const int t = threadIdx.x;
    const int warp = t >> 5, lane = t & 31;
    const int wm = warp >> 2, wn = warp & 3;  // 2x4 warp grid
    const int mh = blockIdx.x;                // E half: rows mh*128..+128
    const int n = blockIdx.y >> 5, l0 = (int)(blockIdx.y & 31) * 128;
    const uint32_t oE[2] = {sb, sb + 18432};
    const uint32_t oBb[2] = {sb + 36864, sb + 36864 + 17408};
    const uint32_t offBb[2] = {36864u, 36864u + 17408u};

    const char* Eg = (const char*)(g_Ebf + (size_t)mh * 128 * 256);
    const float4* XV = (const float4*)(X + (size_t)n * Cdim * Ldim + l0);

    auto cpE = [&](int kc) {
#pragma unroll
        for (int i = 0; i < 4; ++i) {
            int slot = t + 256 * i, row = slot >> 3, c16 = (slot & 7) * 16;
            cpasync16(oE[kc & 1] + row * WPA + c16, Eg + (size_t)row * 512 + kc * 128 + c16);
        }
    };
    float4 rb[8];
    auto loadB = [&](int kc) {
#pragma unroll
        for (int i = 0; i < 4; ++i) {
            int ps = t + 256 * i, row = ps >> 4, j = ps & 15;
            rb[2 * i]     = XV[(size_t)(kc * 64 + row) * 1024 + 2 * j];
            rb[2 * i + 1] = XV[(size_t)(kc * 64 + row) * 1024 + 2 * j + 1];
        }
    };
    auto stsB = [&](int b) {
#pragma unroll
        for (int i = 0; i < 4; ++i) {
            int ps = t + 256 * i, row = ps >> 4, j = ps & 15;
            *(uint4*)(sm + offBb[b] + row * WPB + j * 16) = pack_bf16(rb[2 * i], rb[2 * i + 1]);
        }
    };

    cpE(0); cpcommit();
    cpE(1); cpcommit();
    loadB(0);
    stsB(0);

    float acc[4][4][4];
#pragma unroll
    for (int i = 0; i < 4; ++i)
#pragma unroll
        for (int j = 0; j < 4; ++j)
#pragma unroll
            for (int r = 0; r < 4; ++r) acc[i][j][r] = 0.0f;

    for (int kc = 0; kc < 4; ++kc) {
        if (kc == 3) cpwait<0>(); else cpwait<1>();
        __syncthreads();
        if (kc < 3) loadB(kc + 1);
#pragma unroll
        for (int ks = 0; ks < 4; ++ks) {
            uint32_t af[4][4], bf2[4][2];
#pragma unroll
            for (int mi = 0; mi < 4; ++mi)
                ldsm4(af[mi], oE[kc & 1] + (wm * 64 + mi * 16 + (lane & 15)) * WPA +
                                  ks * 32 + ((lane >> 4) * 16));
#pragma unroll
            for (int ni = 0; ni < 4; ++ni)
                ldsm2t(bf2[ni], oBb[kc & 1] + (ks * 16 + (lane & 15)) * WPB +
                                    (wn * 32 + ni * 8) * 2);
#pragma unroll
            for (int mi = 0; mi < 4; ++mi)
#pragma unroll
                for (int ni = 0; ni < 4; ++ni)
                    mma16816(acc[mi][ni], af[mi], bf2[ni]);
        }
        if (kc < 3) stsB((kc + 1) & 1);
        __syncthreads();
        if (kc < 2) { cpE(kc + 2); cpcommit(); }
    }

    // epilogue: out[c][l] = acc + x - b  (x re-read hits L2)
#pragma unroll
    for (int mi = 0; mi < 4; ++mi) {
        const int r0 = mh * 128 + wm * 64 + mi * 16 + (lane >> 2);
        const float b0 = g_b[r0], b1 = g_b[r0 + 8];
        const float* x0 = X + ((size_t)n * Cdim + r0) * Ldim + l0;
        float* o0 = out + ((size_t)n * Cdim + r0) * Ldim + l0;
#pragma unroll
        for (int ni = 0; ni < 4; ++ni) {
            const int c = wn * 32 + ni * 8 + (lane & 3) * 2;
            float2 xv0 = *(const float2*)(x0 + c);
            float2 xv1 = *(const float2*)(x0 + 8 * Ldim + c);
            float2 ov0, ov1;
            ov0.x = acc[mi][ni][0] + xv0.x - b0;
            ov0.y = acc[mi][ni][1] + xv0.y - b0;
            ov1.x = acc[mi][ni][2] + xv1.x - b1;
            ov1.y = acc[mi][ni][3] + xv1.y - b1;
            *(float2*)(o0 + c) = ov0;
            *(float2*)(o0 + 8 * Ldim + c) = ov1;
        }
    }
}

// ---------------- launch ----------------
extern "C" void kernel_launch(void* const* d_in, const int* in_sizes, int n_in,
                              void* d_out, int out_size) {
    const float* X = (const float*)d_in[0];
    float* out = (float*)d_out;

    cudaFuncSetAttribute(gram_kernel, cudaFuncAttributeMaxDynamicSharedMemorySize, 73728);
    cudaFuncSetAttribute(whiten_kernel, cudaFuncAttributeMaxDynamicSharedMemorySize, 71680);

    gram_kernel<<<dim3(3, 64, 2), 256, 73728>>>(X);
    mean_reduce<<<1, 256>>>();
    sigma_kernel<<<256, 256>>>();
    trace_kernel<<<1, 256>>>();
    e0_kernel<<<256, 256>>>();
    poly1<<<16, 256>>>();
    poly2<<<16, 256>>>();
    poly3<<<16, 256>>>();
    bE_kernel<<<256, 256>>>();
    whiten_kernel<<<dim3(2, 2048), 256, 71680>>>(X, out);
}

// round 8
// speedup vs baseline: 1.4452x; 1.4452x over previous
#include <cuda_runtime.h>
#include <cuda_bf16.h>
#include <cstdint>

#define Cdim 256
#define Ldim 4096
#define Nb   64
#define MTOT (Nb * Ldim)

// ---------------- static device scratch ----------------
__device__ __nv_bfloat16 g_Xh[(size_t)Nb * Cdim * Ldim];  // 128 MB bf16 copy of X
__device__ float g_part[3][128][128 * 128];               // gram partials (tile, n*2+kh)
__device__ float g_msum[Cdim * Nb];
__device__ float g_mean[Cdim];
__device__ float g_sigma[Cdim * Cdim];
__device__ float g_scal[4];
__device__ float g_NS[5][Cdim * Cdim];        // 0:E0 1:E2 2:Bmat/Zn 3:amat 4:G
__device__ __nv_bfloat16 g_Ebf[Cdim * Cdim];  // E = scal1*Zn - I in bf16
__device__ float g_b[Cdim];

// ---------------- PTX helpers (plain sm_80+ features only) ----------------
__device__ __forceinline__ uint32_t smem_u32(const void* p) {
    uint32_t a;
    asm("{ .reg .u64 t; cvta.to.shared.u64 t, %1; cvt.u32.u64 %0, t; }" : "=r"(a) : "l"(p));
    return a;
}
__device__ __forceinline__ void mma16816(float* d, const uint32_t* a, const uint32_t* b) {
    asm volatile(
        "mma.sync.aligned.m16n8k16.row.col.f32.bf16.bf16.f32 "
        "{%0,%1,%2,%3}, {%4,%5,%6,%7}, {%8,%9}, {%0,%1,%2,%3};"
        : "+f"(d[0]), "+f"(d[1]), "+f"(d[2]), "+f"(d[3])
        : "r"(a[0]), "r"(a[1]), "r"(a[2]), "r"(a[3]), "r"(b[0]), "r"(b[1]));
}
__device__ __forceinline__ void ldsm4(uint32_t* r, uint32_t addr) {
    asm volatile("ldmatrix.sync.aligned.m8n8.x4.shared.b16 {%0,%1,%2,%3}, [%4];"
                 : "=r"(r[0]), "=r"(r[1]), "=r"(r[2]), "=r"(r[3]) : "r"(addr));
}
__device__ __forceinline__ void ldsm2(uint32_t* r, uint32_t addr) {
    asm volatile("ldmatrix.sync.aligned.m8n8.x2.shared.b16 {%0,%1}, [%2];"
                 : "=r"(r[0]), "=r"(r[1]) : "r"(addr));
}
__device__ __forceinline__ void ldsm2t(uint32_t* r, uint32_t addr) {
    asm volatile("ldmatrix.sync.aligned.m8n8.x2.trans.shared.b16 {%0,%1}, [%2];"
                 : "=r"(r[0]), "=r"(r[1]) : "r"(addr));
}
__device__ __forceinline__ void cpasync16(uint32_t smem, const void* g) {
    asm volatile("cp.async.cg.shared.global [%0], [%1], 16;" :: "r"(smem), "l"(g));
}
__device__ __forceinline__ void cpcommit() { asm volatile("cp.async.commit_group;" ::: "memory"); }
template <int N>
__device__ __forceinline__ void cpwait() {
    asm volatile("cp.async.wait_group %0;" :: "n"(N) : "memory");
}

// ---------------- 1) convert X -> bf16, per-row partial sums ----------------
__global__ void conv_kernel(const float* __restrict__ X) {
    const size_t row = blockIdx.x;  // n*Cdim + c
    const int t = threadIdx.x;
    const float4* src = (const float4*)(X + row * (size_t)Ldim);
    uint4* dst = (uint4*)(g_Xh + row * (size_t)Ldim);
    float s = 0.0f;
#pragma unroll
    for (int i = 0; i < 2; ++i) {
        float4 a = src[4 * t + 2 * i];
        float4 b = src[4 * t + 2 * i + 1];
        s += a.x + a.y + a.z + a.w + b.x + b.y + b.z + b.w;
        uint4 o;
        __nv_bfloat162 h;
        h = __floats2bfloat162_rn(a.x, a.y); o.x = *(uint32_t*)&h;
        h = __floats2bfloat162_rn(a.z, a.w); o.y = *(uint32_t*)&h;
        h = __floats2bfloat162_rn(b.x, b.y); o.z = *(uint32_t*)&h;
        h = __floats2bfloat162_rn(b.z, b.w); o.w = *(uint32_t*)&h;
        dst[2 * t + i] = o;
    }
    __shared__ float red[256];
    red[t] = s;
    __syncthreads();
    for (int o = 128; o > 0; o >>= 1) {
        if (t < o) red[t] += red[t + o];
        __syncthreads();
    }
    if (t == 0) g_msum[row] = red[0];
}

__global__ void mean_reduce() {
    const int c = threadIdx.x;
    float s = 0.0f;
    for (int n = 0; n < Nb; ++n) s += g_msum[(size_t)n * Cdim + c];
    g_mean[c] = s * (1.0f / (float)MTOT);
}

// ---------------- 2) Gram via mma.sync: 3 tiles x 64 n x 2 k-halves ----------------
#define GP 144  // gram smem row pitch (64 bf16 = 128B + 16B pad)
__device__ __forceinline__ void gram_prefetch(uint32_t offA, uint32_t offB,
                                              const char* Ag, const char* Bg,
                                              int t, int kb, bool diag) {
#pragma unroll
    for (int i = 0; i < 4; ++i) {
        int slot = t + 256 * i;
        int row = slot >> 3, c16 = (slot & 7) * 16;
        cpasync16(offA + row * GP + c16, Ag + (size_t)row * 8192 + kb + c16);
        if (!diag)
            cpasync16(offB + row * GP + c16, Bg + (size_t)row * 8192 + kb + c16);
    }
}

__global__ __launch_bounds__(256) void gram_kernel() {
    extern __shared__ __align__(128) char sm[];
    const uint32_t sb = smem_u32(sm);
    const int t = threadIdx.x;
    const int warp = t >> 5, lane = t & 31;
    const int wm = warp >> 2, wn = warp & 3;  // 2 x 4 warp grid, warp tile 64x32
    const int tile = blockIdx.x, n = blockIdx.y, kh = blockIdx.z;
    const int ti = (tile == 0) ? 0 : 1;
    const int tj = (tile == 2) ? 1 : 0;
    const bool diag = (tile != 1);
    const uint32_t offA[2] = {sb, sb + 36864};
    const uint32_t offB[2] = {sb + 18432, sb + 55296};
    const int kbase = kh * 4096;  // byte offset along K (2048 bf16)

    const char* Ag = (const char*)(g_Xh + ((size_t)n * Cdim + ti * 128) * Ldim) + kbase;
    const char* Bg = (const char*)(g_Xh + ((size_t)n * Cdim + tj * 128) * Ldim) + kbase;

    float acc[4][4][4];
#pragma unroll
    for (int i = 0; i < 4; ++i)
#pragma unroll
        for (int j = 0; j < 4; ++j)
#pragma unroll
            for (int r = 0; r < 4; ++r) acc[i][j][r] = 0.0f;

    gram_prefetch(offA[0], offB[0], Ag, Bg, t, 0, diag);
    cpcommit();
    gram_prefetch(offA[1], offB[1], Ag, Bg, t, 128, diag);
    cpcommit();

    for (int s = 0; s < 32; ++s) {
        if (s == 31) cpwait<0>(); else cpwait<1>();
        __syncthreads();
        const uint32_t sa = offA[s & 1];
        const uint32_t sbuf = diag ? sa : offB[s & 1];
#pragma unroll
        for (int ks = 0; ks < 4; ++ks) {
            uint32_t afrag[4][4], bfrag[4][2];
#pragma unroll
            for (int mi = 0; mi < 4; ++mi)
                ldsm4(afrag[mi], sa + (wm * 64 + mi * 16 + (lane & 15)) * GP +
                                     ks * 32 + ((lane >> 4) * 16));
#pragma unroll
            for (int ni = 0; ni < 4; ++ni)
                ldsm2(bfrag[ni], sbuf + (wn * 32 + ni * 8 + (lane & 7)) * GP +
                                     ks * 32 + (((lane >> 3) & 1) * 16));
#pragma unroll
            for (int mi = 0; mi < 4; ++mi)
#pragma unroll
                for (int ni = 0; ni < 4; ++ni)
                    mma16816(acc[mi][ni], afrag[mi], bfrag[ni]);
        }
        __syncthreads();
        if (s + 2 < 32) {
            gram_prefetch(offA[s & 1], offB[s & 1], Ag, Bg, t, (s + 2) * 128, diag);
            cpcommit();
        }
    }

    float* outp = g_part[tile][n * 2 + kh];
#pragma unroll
    for (int mi = 0; mi < 4; ++mi)
#pragma unroll
        for (int ni = 0; ni < 4; ++ni) {
            int r0 = wm * 64 + mi * 16 + (lane >> 2);
            int c0 = wn * 32 + ni * 8 + (lane & 3) * 2;
            *(float2*)(outp + r0 * 128 + c0)       = make_float2(acc[mi][ni][0], acc[mi][ni][1]);
            *(float2*)(outp + (r0 + 8) * 128 + c0) = make_float2(acc[mi][ni][2], acc[mi][ni][3]);
        }
}

// ---------------- 3) sigma assembly (deterministic reduce over 128 splits) ----------------
__global__ void sigma_kernel() {
    const int idx = blockIdx.x * 256 + threadIdx.x;
    const int i = idx >> 8, j = idx & 255;
    int tile, ii, jj;
    if (i < 128 && j < 128)        { tile = 0; ii = i;       jj = j; }
    else if (i >= 128 && j < 128)  { tile = 1; ii = i - 128; jj = j; }
    else if (i >= 128 && j >= 128) { tile = 2; ii = i - 128; jj = j - 128; }
    else                           { tile = 1; ii = j - 128; jj = i; }  // symmetry
    float s = 0.0f;
#pragma unroll 16
    for (int p = 0; p < 128; ++p) s += g_part[tile][p][ii * 128 + jj];
    float v = s * (1.0f / (float)MTOT) - g_mean[i] * g_mean[j];
    if (i == j) v += 1e-3f;
    g_sigma[idx] = v;
}

__global__ void trace_kernel() {
    __shared__ float red[256];
    const int t = threadIdx.x;
    red[t] = g_sigma[t * 257];
    __syncthreads();
    for (int o = 128; o > 0; o >>= 1) {
        if (t < o) red[t] += red[t + o];
        __syncthreads();
    }
    if (t == 0) {
        float s = red[0] * (1.0f / 256.0f);
        g_scal[0] = 1.0f / s;
        g_scal[1] = rsqrtf(s);
    }
}

__global__ void e0_kernel() {  // E0 = sigma/s - I
    const int idx = blockIdx.x * 256 + threadIdx.x;
    g_NS[0][idx] = g_sigma[idx] * g_scal[0] - (((idx >> 8) == (idx & 255)) ? 1.0f : 0.0f);
}

// ---------------- 4) fp32 256^3 GEMM core for polynomial inverse-sqrt ----------------
__device__ __forceinline__ void ns_core(const float* A, const float* B, float acc[4][4]) {
    const int ti = blockIdx.x >> 2, tj = blockIdx.x & 3;
    __shared__ float As[64][17];
    __shared__ float Bs[16][68];
    const int t = threadIdx.x;
    const int tx = t & 15, ty = t >> 4;
    for (int k0 = 0; k0 < 256; k0 += 16) {
        float4 av = *(const float4*)(A + (size_t)(ti * 64 + (t >> 2)) * 256 + k0 + ((t & 3) << 2));
        float4 bv = *(const float4*)(B + (size_t)(k0 + (t >> 4)) * 256 + tj * 64 + ((t & 15) << 2));
        __syncthreads();
        {
            const int ar = t >> 2, ak = (t & 3) << 2;
            As[ar][ak + 0] = av.x; As[ar][ak + 1] = av.y; As[ar][ak + 2] = av.z; As[ar][ak + 3] = av.w;
            *(float4*)&Bs[t >> 4][(t & 15) << 2] = bv;
        }
        __syncthreads();
#pragma unroll
        for (int k = 0; k < 16; ++k) {
            float4 b = *(const float4*)&Bs[k][tx << 2];
            float a0 = As[ty * 4 + 0][k], a1 = As[ty * 4 + 1][k];
            float a2 = As[ty * 4 + 2][k], a3 = As[ty * 4 + 3][k];
            acc[0][0] += a0 * b.x; acc[0][1] += a0 * b.y; acc[0][2] += a0 * b.z; acc[0][3] += a0 * b.w;
            acc[1][0] += a1 * b.x; acc[1][1] += a1 * b.y; acc[1][2] += a1 * b.z; acc[1][3] += a1 * b.w;
            acc[2][0] += a2 * b.x; acc[2][1] += a2 * b.y; acc[2][2] += a2 * b.z; acc[2][3] += a2 * b.w;
            acc[3][0] += a3 * b.x; acc[3][1] += a3 * b.y; acc[3][2] += a3 * b.z; acc[3][3] += a3 * b.w;
        }
    }
}

// Taylor of (1+x)^{-1/2}: 1, -1/2, 3/8, -5/16, 35/128, -63/256
__global__ void poly1() {  // E2 = E0@E0; amat = I - .5 E0 + .375 E2; Bmat = c3 I + c4 E0 + c5 E2
    float acc[4][4] = {};
    ns_core(g_NS[0], g_NS[0], acc);
    const int ti = blockIdx.x >> 2, tj = blockIdx.x & 3;
    const int t = threadIdx.x, tx = t & 15, ty = t >> 4;
#pragma unroll
    for (int i = 0; i < 4; ++i)
#pragma unroll
        for (int j = 0; j < 4; ++j) {
            const int gi = ti * 64 + ty * 4 + i, gj = tj * 64 + tx * 4 + j;
            const float d = (gi == gj) ? 1.0f : 0.0f;
            const float e0 = g_NS[0][gi * 256 + gj];
            const float e2 = acc[i][j];
            g_NS[1][gi * 256 + gj] = e2;
            g_NS[3][gi * 256 + gj] = d - 0.5f * e0 + 0.375f * e2;
            g_NS[2][gi * 256 + gj] = -0.3125f * d + 0.2734375f * e0 - 0.24609375f * e2;
        }
}
__global__ void poly2() {  // G = E2 @ Bmat
    float acc[4][4] = {};
    ns_core(g_NS[1], g_NS[2], acc);
    const int ti = blockIdx.x >> 2, tj = blockIdx.x & 3;
    const int t = threadIdx.x, tx = t & 15, ty = t >> 4;
#pragma unroll
    for (int i = 0; i < 4; ++i)
#pragma unroll
        for (int j = 0; j < 4; ++j)
            g_NS[4][(ti * 64 + ty * 4 + i) * 256 + tj * 64 + tx * 4 + j] = acc[i][j];
}
__global__ void poly3() {  // Zn = E0 @ G + amat  -> g_NS[2]
    float acc[4][4] = {};
    ns_core(g_NS[0], g_NS[4], acc);
    const int ti = blockIdx.x >> 2, tj = blockIdx.x & 3;
    const int t = threadIdx.x, tx = t & 15, ty = t >> 4;
#pragma unroll
    for (int i = 0; i < 4; ++i)
#pragma unroll
        for (int j = 0; j < 4; ++j) {
            const int gi = ti * 64 + ty * 4 + i, gj = tj * 64 + tx * 4 + j;
            g_NS[2][gi * 256 + gj] = acc[i][j] + g_NS[3][gi * 256 + gj];
        }
}

// ---------------- 5) E = scal1*Zn - I (bf16) and b = mu + E mu ----------------
__global__ void bE_kernel() {
    const int c = blockIdx.x, t = threadIdx.x;
    const float sc = g_scal[1];
    float e = sc * g_NS[2][c * 256 + t] - ((c == t) ? 1.0f : 0.0f);
    g_Ebf[c * 256 + t] = __float2bfloat16(e);
    __shared__ float red[256];
    red[t] = e * g_mean[t];
    __syncthreads();
    for (int o = 128; o > 0; o >>= 1) {
        if (t < o) red[t] += red[t + o];
        __syncthreads();
    }
    if (t == 0) g_b[c] = g_mean[c] + red[0];
}

// ---------------- 6) whiten: out = x - b + E @ x_bf16 (K-pipelined mma.sync) ----------------
#define WPA 144  // E chunk pitch: 64 bf16 = 128B + 16
#define WPB 272  // x chunk pitch: 128 bf16 = 256B + 16
#define WSA (256 * WPA)          // 36864
#define WSB (64 * WPB)           // 17408
#define WSTAGE (WSA + WSB)       // 54272

__device__ __forceinline__ void whiten_prefetch(uint32_t offA, uint32_t offB,
                                                const char* Eg, const char* Bg,
                                                int t, int kc) {
#pragma unroll
    for (int i = 0; i < 4; ++i) {
        int slot = t + 512 * i;
        int row = slot >> 3, c16 = (slot & 7) * 16;
        cpasync16(offA + row * WPA + c16, Eg + (size_t)row * 512 + kc * 128 + c16);
    }
#pragma unroll
    for (int i = 0; i < 2; ++i) {
        int slot = t + 512 * i;
        int row = slot >> 4, c16 = (slot & 15) * 16;
        cpasync16(offB + row * WPB + c16, Bg + (size_t)(kc * 64 + row) * 8192 + c16);
    }
}

__global__ __launch_bounds__(512) void whiten_kernel(const float* __restrict__ X,
                                                     float* __restrict__ out) {
    extern __shared__ __align__(128) char sm[];
    const uint32_t sb = smem_u32(sm);
    const int t = threadIdx.x;
    const int warp = t >> 5, lane = t & 31;
    const int wm = warp >> 2, wn = warp & 3;  // 4 x 4 warp grid, warp tile 64x32
    const int n = blockIdx.x >> 5, l0 = (blockIdx.x & 31) * 128;
    const uint32_t offA[2] = {sb, sb + WSTAGE};
    const uint32_t offB[2] = {sb + WSA, sb + WSTAGE + WSA};

    const char* Eg = (const char*)g_Ebf;
    const char* Bg = (const char*)(g_Xh + (size_t)n * Cdim * Ldim + l0);

    float acc[4][4][4];
#pragma unroll
    for (int i = 0; i < 4; ++i)
#pragma unroll
        for (int j = 0; j < 4; ++j)
#pragma unroll
            for (int r = 0; r < 4; ++r) acc[i][j][r] = 0.0f;

    whiten_prefetch(offA[0], offB[0], Eg, Bg, t, 0);
    cpcommit();
    whiten_prefetch(offA[1], offB[1], Eg, Bg, t, 1);
    cpcommit();

    for (int kc = 0; kc < 4; ++kc) {
        if (kc == 3) cpwait<0>(); else cpwait<1>();
        __syncthreads();
        const uint32_t sA = offA[kc & 1], sB = offB[kc & 1];
#pragma unroll
        for (int ks = 0; ks < 4; ++ks) {
            uint32_t afrag[4][4], bfrag[4][2];
#pragma unroll
            for (int mi = 0; mi < 4; ++mi)
                ldsm4(afrag[mi], sA + (wm * 64 + mi * 16 + (lane & 15)) * WPA +
                                     ks * 32 + ((lane >> 4) * 16));
#pragma unroll
            for (int ni = 0; ni < 4; ++ni)
                ldsm2t(bfrag[ni], sB + (ks * 16 + (lane & 15)) * WPB +
                                      (wn * 32 + ni * 8) * 2);
#pragma unroll
            for (int mi = 0; mi < 4; ++mi)
#pragma unroll
                for (int ni = 0; ni < 4; ++ni)
                    mma16816(acc[mi][ni], afrag[mi], bfrag[ni]);
        }
        __syncthreads();
        if (kc + 2 < 4) {
            whiten_prefetch(offA[kc & 1], offB[kc & 1], Eg, Bg, t, kc + 2);
            cpcommit();
        }
    }

    // epilogue: out[c][l] = acc + x - b
#pragma unroll
    for (int mi = 0; mi < 4; ++mi) {
        const int r0 = wm * 64 + mi * 16 + (lane >> 2);
        const float b0 = g_b[r0], b1 = g_b[r0 + 8];
        const float* x0 = X + ((size_t)n * Cdim + r0) * Ldim + l0;
        float* o0 = out + ((size_t)n * Cdim + r0) * Ldim + l0;
#pragma unroll
        for (int ni = 0; ni < 4; ++ni) {
            const int c = wn * 32 + ni * 8 + (lane & 3) * 2;
            float2 xv0 = *(const float2*)(x0 + c);
            float2 xv1 = *(const float2*)(x0 + 8 * Ldim + c);
            float2 ov0, ov1;
            ov0.x = acc[mi][ni][0] + xv0.x - b0;
            ov0.y = acc[mi][ni][1] + xv0.y - b0;
            ov1.x = acc[mi][ni][2] + xv1.x - b1;
            ov1.y = acc[mi][ni][3] + xv1.y - b1;
            *(float2*)(o0 + c) = ov0;
            *(float2*)(o0 + 8 * Ldim + c) = ov1;
        }
    }
}

// ---------------- launch ----------------
extern "C" void kernel_launch(void* const* d_in, const int* in_sizes, int n_in,
                              void* d_out, int out_size) {
    const float* X = (const float*)d_in[0];
    float* out = (float*)d_out;

    cudaFuncSetAttribute(gram_kernel, cudaFuncAttributeMaxDynamicSharedMemorySize, 73728);
    cudaFuncSetAttribute(whiten_kernel, cudaFuncAttributeMaxDynamicSharedMemorySize, 2 * WSTAGE);

    conv_kernel<<<Nb * Cdim, 256>>>(X);
    mean_reduce<<<1, 256>>>();
    gram_kernel<<<dim3(3, 64, 2), 256, 73728>>>();
    sigma_kernel<<<256, 256>>>();
    trace_kernel<<<1, 256>>>();
    e0_kernel<<<256, 256>>>();
    poly1<<<16, 256>>>();
    poly2<<<16, 256>>>();
    poly3<<<16, 256>>>();
    bE_kernel<<<256, 256>>>();
    whiten_kernel<<<2048, 512, 2 * WSTAGE>>>(X, out);
}

// round 9
// speedup vs baseline: 1.5040x; 1.0407x over previous
#include <cuda_runtime.h>
#include <cuda_bf16.h>
#include <cstdint>

#define Cdim 256
#define Ldim 4096
#define Nb   64
#define MTOT (Nb * Ldim)

// ---------------- static device scratch ----------------
__device__ __nv_bfloat16 g_Xh[(size_t)Nb * Cdim * Ldim];  // 128 MB bf16 copy of X (gram only)
__device__ float g_part[3][128][128 * 128];               // gram partials (tile, n*2+kh)
__device__ float g_msum[Cdim * Nb];
__device__ float g_mean[Cdim];
__device__ float g_sigma[Cdim * Cdim];
__device__ float g_scal[4];
__device__ float g_NS[5][Cdim * Cdim];        // 0:E0 1:E2 2:Bmat/Zn 3:amat 4:G
__device__ __nv_bfloat16 g_Ebf[Cdim * Cdim];  // E = scal1*Zn - I in bf16
__device__ float g_b[Cdim];

// ---------------- PTX helpers (plain sm_80+ features only) ----------------
__device__ __forceinline__ uint32_t smem_u32(const void* p) {
    uint32_t a;
    asm("{ .reg .u64 t; cvta.to.shared.u64 t, %1; cvt.u32.u64 %0, t; }" : "=r"(a) : "l"(p));
    return a;
}
__device__ __forceinline__ void mma16816(float* d, const uint32_t* a, const uint32_t* b) {
    asm volatile(
        "mma.sync.aligned.m16n8k16.row.col.f32.bf16.bf16.f32 "
        "{%0,%1,%2,%3}, {%4,%5,%6,%7}, {%8,%9}, {%0,%1,%2,%3};"
        : "+f"(d[0]), "+f"(d[1]), "+f"(d[2]), "+f"(d[3])
        : "r"(a[0]), "r"(a[1]), "r"(a[2]), "r"(a[3]), "r"(b[0]), "r"(b[1]));
}
__device__ __forceinline__ void ldsm4(uint32_t* r, uint32_t addr) {
    asm volatile("ldmatrix.sync.aligned.m8n8.x4.shared.b16 {%0,%1,%2,%3}, [%4];"
                 : "=r"(r[0]), "=r"(r[1]), "=r"(r[2]), "=r"(r[3]) : "r"(addr));
}
__device__ __forceinline__ void ldsm2(uint32_t* r, uint32_t addr) {
    asm volatile("ldmatrix.sync.aligned.m8n8.x2.shared.b16 {%0,%1}, [%2];"
                 : "=r"(r[0]), "=r"(r[1]) : "r"(addr));
}
__device__ __forceinline__ void cpasync16(uint32_t smem, const void* g) {
    asm volatile("cp.async.cg.shared.global [%0], [%1], 16;" :: "r"(smem), "l"(g));
}
__device__ __forceinline__ void cpcommit() { asm volatile("cp.async.commit_group;" ::: "memory"); }
template <int N>
__device__ __forceinline__ void cpwait() {
    asm volatile("cp.async.wait_group %0;" :: "n"(N) : "memory");
}

// ---------------- 1) convert X -> bf16, per-row partial sums ----------------
__global__ void conv_kernel(const float* __restrict__ X) {
    const size_t row = blockIdx.x;  // n*Cdim + c
    const int t = threadIdx.x;
    const float4* src = (const float4*)(X + row * (size_t)Ldim);
    uint4* dst = (uint4*)(g_Xh + row * (size_t)Ldim);
    float s = 0.0f;
#pragma unroll
    for (int i = 0; i < 2; ++i) {
        float4 a = src[4 * t + 2 * i];
        float4 b = src[4 * t + 2 * i + 1];
        s += a.x + a.y + a.z + a.w + b.x + b.y + b.z + b.w;
        uint4 o;
        __nv_bfloat162 h;
        h = __floats2bfloat162_rn(a.x, a.y); o.x = *(uint32_t*)&h;
        h = __floats2bfloat162_rn(a.z, a.w); o.y = *(uint32_t*)&h;
        h = __floats2bfloat162_rn(b.x, b.y); o.z = *(uint32_t*)&h;
        h = __floats2bfloat162_rn(b.z, b.w); o.w = *(uint32_t*)&h;
        dst[2 * t + i] = o;
    }
    __shared__ float red[256];
    red[t] = s;
    __syncthreads();
    for (int o = 128; o > 0; o >>= 1) {
        if (t < o) red[t] += red[t + o];
        __syncthreads();
    }
    if (t == 0) g_msum[row] = red[0];
}

__global__ void mean_reduce() {
    const int c = threadIdx.x;
    float s = 0.0f;
    for (int n = 0; n < Nb; ++n) s += g_msum[(size_t)n * Cdim + c];
    g_mean[c] = s * (1.0f / (float)MTOT);
}

// ---------------- 2) Gram via mma.sync: 3 tiles x 64 n x 2 k-halves ----------------
#define GP 144  // gram smem row pitch (64 bf16 = 128B + 16B pad)
__device__ __forceinline__ void gram_prefetch(uint32_t offA, uint32_t offB,
                                              const char* Ag, const char* Bg,
                                              int t, int kb, bool diag) {
#pragma unroll
    for (int i = 0; i < 4; ++i) {
        int slot = t + 256 * i;
        int row = slot >> 3, c16 = (slot & 7) * 16;
        cpasync16(offA + row * GP + c16, Ag + (size_t)row * 8192 + kb + c16);
        if (!diag)
            cpasync16(offB + row * GP + c16, Bg + (size_t)row * 8192 + kb + c16);
    }
}

__global__ __launch_bounds__(256) void gram_kernel() {
    extern __shared__ __align__(128) char sm[];
    const uint32_t sb = smem_u32(sm);
    const int t = threadIdx.x;
    const int warp = t >> 5, lane = t & 31;
    const int wm = warp >> 2, wn = warp & 3;  // 2 x 4 warp grid, warp tile 64x32
    const int tile = blockIdx.x, n = blockIdx.y, kh = blockIdx.z;
    const int ti = (tile == 0) ? 0 : 1;
    const int tj = (tile == 2) ? 1 : 0;
    const bool diag = (tile != 1);
    const uint32_t offA[2] = {sb, sb + 36864};
    const uint32_t offB[2] = {sb + 18432, sb + 55296};
    const int kbase = kh * 4096;  // byte offset along K (2048 bf16)

    const char* Ag = (const char*)(g_Xh + ((size_t)n * Cdim + ti * 128) * Ldim) + kbase;
    const char* Bg = (const char*)(g_Xh + ((size_t)n * Cdim + tj * 128) * Ldim) + kbase;

    float acc[4][4][4];
#pragma unroll
    for (int i = 0; i < 4; ++i)
#pragma unroll
        for (int j = 0; j < 4; ++j)
#pragma unroll
            for (int r = 0; r < 4; ++r) acc[i][j][r] = 0.0f;

    gram_prefetch(offA[0], offB[0], Ag, Bg, t, 0, diag);
    cpcommit();
    gram_prefetch(offA[1], offB[1], Ag, Bg, t, 128, diag);
    cpcommit();

    for (int s = 0; s < 32; ++s) {
        if (s == 31) cpwait<0>(); else cpwait<1>();
        __syncthreads();
        const uint32_t sa = offA[s & 1];
        const uint32_t sbuf = diag ? sa : offB[s & 1];
#pragma unroll
        for (int ks = 0; ks < 4; ++ks) {
            uint32_t afrag[4][4], bfrag[4][2];
#pragma unroll
            for (int mi = 0; mi < 4; ++mi)
                ldsm4(afrag[mi], sa + (wm * 64 + mi * 16 + (lane & 15)) * GP +
                                     ks * 32 + ((lane >> 4) * 16));
#pragma unroll
            for (int ni = 0; ni < 4; ++ni)
                ldsm2(bfrag[ni], sbuf + (wn * 32 + ni * 8 + (lane & 7)) * GP +
                                     ks * 32 + (((lane >> 3) & 1) * 16));
#pragma unroll
            for (int mi = 0; mi < 4; ++mi)
#pragma unroll
                for (int ni = 0; ni < 4; ++ni)
                    mma16816(acc[mi][ni], afrag[mi], bfrag[ni]);
        }
        __syncthreads();
        if (s + 2 < 32) {
            gram_prefetch(offA[s & 1], offB[s & 1], Ag, Bg, t, (s + 2) * 128, diag);
            cpcommit();
        }
    }

    float* outp = g_part[tile][n * 2 + kh];
#pragma unroll
    for (int mi = 0; mi < 4; ++mi)
#pragma unroll
        for (int ni = 0; ni < 4; ++ni) {
            int r0 = wm * 64 + mi * 16 + (lane >> 2);
            int c0 = wn * 32 + ni * 8 + (lane & 3) * 2;
            *(float2*)(outp + r0 * 128 + c0)       = make_float2(acc[mi][ni][0], acc[mi][ni][1]);
            *(float2*)(outp + (r0 + 8) * 128 + c0) = make_float2(acc[mi][ni][2], acc[mi][ni][3]);
        }
}

// ---------------- 3) sigma assembly (float4, deterministic reduce, 128 splits) ----------------
__global__ void sigma_kernel() {
    const int q = blockIdx.x * 128 + threadIdx.x;  // 0..16383
    const int i = q >> 6;
    const int j0 = (q & 63) * 4;
    float sx = 0.0f, sy = 0.0f, sz = 0.0f, sw = 0.0f;
    if (i < 128 && j0 >= 128) {
        // mirrored quadrant: value(i, j) = tile1[j-128][i]
        const int jb = (j0 - 128) * 128 + i;
#pragma unroll 8
        for (int p = 0; p < 128; ++p) {
            const float* base = g_part[1][p];
            sx += base[jb];
            sy += base[jb + 128];
            sz += base[jb + 256];
            sw += base[jb + 384];
        }
    } else {
        const int tile = (i < 128) ? 0 : ((j0 < 128) ? 1 : 2);
        const int ii = (i < 128) ? i : i - 128;
        const int jj = (j0 < 128) ? j0 : j0 - 128;
        const float* base0 = g_part[tile][0] + ii * 128 + jj;
#pragma unroll 8
        for (int p = 0; p < 128; ++p) {
            float4 v = *(const float4*)(base0 + (size_t)p * 16384);
            sx += v.x; sy += v.y; sz += v.z; sw += v.w;
        }
    }
    const float inv = 1.0f / (float)MTOT;
    const float mi_ = g_mean[i];
    float vx = sx * inv - mi_ * g_mean[j0 + 0];
    float vy = sy * inv - mi_ * g_mean[j0 + 1];
    float vz = sz * inv - mi_ * g_mean[j0 + 2];
    float vw = sw * inv - mi_ * g_mean[j0 + 3];
    if (i == j0 + 0) vx += 1e-3f;
    if (i == j0 + 1) vy += 1e-3f;
    if (i == j0 + 2) vz += 1e-3f;
    if (i == j0 + 3) vw += 1e-3f;
    *(float4*)(g_sigma + i * 256 + j0) = make_float4(vx, vy, vz, vw);
}

__global__ void trace_kernel() {
    __shared__ float red[256];
    const int t = threadIdx.x;
    red[t] = g_sigma[t * 257];
    __syncthreads();
    for (int o = 128; o > 0; o >>= 1) {
        if (t < o) red[t] += red[t + o];
        __syncthreads();
    }
    if (t == 0) {
        float s = red[0] * (1.0f / 256.0f);
        g_scal[0] = 1.0f / s;
        g_scal[1] = rsqrtf(s);
    }
}

__global__ void e0_kernel() {  // E0 = sigma/s - I
    const int idx = blockIdx.x * 256 + threadIdx.x;
    g_NS[0][idx] = g_sigma[idx] * g_scal[0] - (((idx >> 8) == (idx & 255)) ? 1.0f : 0.0f);
}

// ---------------- 4) fp32 256^3 GEMM core for polynomial inverse-sqrt ----------------
__device__ __forceinline__ void ns_core(const float* A, const float* B, float acc[4][4]) {
    const int ti = blockIdx.x >> 2, tj = blockIdx.x & 3;
    __shared__ float As[64][17];
    __shared__ float Bs[16][68];
    const int t = threadIdx.x;
    const int tx = t & 15, ty = t >> 4;
    for (int k0 = 0; k0 < 256; k0 += 16) {
        float4 av = *(const float4*)(A + (size_t)(ti * 64 + (t >> 2)) * 256 + k0 + ((t & 3) << 2));
        float4 bv = *(const float4*)(B + (size_t)(k0 + (t >> 4)) * 256 + tj * 64 + ((t & 15) << 2));
        __syncthreads();
        {
            const int ar = t >> 2, ak = (t & 3) << 2;
            As[ar][ak + 0] = av.x; As[ar][ak + 1] = av.y; As[ar][ak + 2] = av.z; As[ar][ak + 3] = av.w;
            *(float4*)&Bs[t >> 4][(t & 15) << 2] = bv;
        }
        __syncthreads();
#pragma unroll
        for (int k = 0; k < 16; ++k) {
            float4 b = *(const float4*)&Bs[k][tx << 2];
            float a0 = As[ty * 4 + 0][k], a1 = As[ty * 4 + 1][k];
            float a2 = As[ty * 4 + 2][k], a3 = As[ty * 4 + 3][k];
            acc[0][0] += a0 * b.x; acc[0][1] += a0 * b.y; acc[0][2] += a0 * b.z; acc[0][3] += a0 * b.w;
            acc[1][0] += a1 * b.x; acc[1][1] += a1 * b.y; acc[1][2] += a1 * b.z; acc[1][3] += a1 * b.w;
            acc[2][0] += a2 * b.x; acc[2][1] += a2 * b.y; acc[2][2] += a2 * b.z; acc[2][3] += a2 * b.w;
            acc[3][0] += a3 * b.x; acc[3][1] += a3 * b.y; acc[3][2] += a3 * b.z; acc[3][3] += a3 * b.w;
        }
    }
}

// Taylor of (1+x)^{-1/2}: 1, -1/2, 3/8, -5/16, 35/128, -63/256
__global__ void poly1() {  // E2 = E0@E0; amat = I - .5 E0 + .375 E2; Bmat = c3 I + c4 E0 + c5 E2
    float acc[4][4] = {};
    ns_core(g_NS[0], g_NS[0], acc);
    const int ti = blockIdx.x >> 2, tj = blockIdx.x & 3;
    const int t = threadIdx.x, tx = t & 15, ty = t >> 4;
#pragma unroll
    for (int i = 0; i < 4; ++i)
#pragma unroll
        for (int j = 0; j < 4; ++j) {
            const int gi = ti * 64 + ty * 4 + i, gj = tj * 64 + tx * 4 + j;
            const float d = (gi == gj) ? 1.0f : 0.0f;
            const float e0 = g_NS[0][gi * 256 + gj];
            const float e2 = acc[i][j];
            g_NS[1][gi * 256 + gj] = e2;
            g_NS[3][gi * 256 + gj] = d - 0.5f * e0 + 0.375f * e2;
            g_NS[2][gi * 256 + gj] = -0.3125f * d + 0.2734375f * e0 - 0.24609375f * e2;
        }
}
__global__ void poly2() {  // G = E2 @ Bmat
    float acc[4][4] = {};
    ns_core(g_NS[1], g_NS[2], acc);
    const int ti = blockIdx.x >> 2, tj = blockIdx.x & 3;
    const int t = threadIdx.x, tx = t & 15, ty = t >> 4;
#pragma unroll
    for (int i = 0; i < 4; ++i)
#pragma unroll
        for (int j = 0; j < 4; ++j)
            g_NS[4][(ti * 64 + ty * 4 + i) * 256 + tj * 64 + tx * 4 + j] = acc[i][j];
}
__global__ void poly3() {  // Zn = E0 @ G + amat  -> g_NS[2]
    float acc[4][4] = {};
    ns_core(g_NS[0], g_NS[4], acc);
    const int ti = blockIdx.x >> 2, tj = blockIdx.x & 3;
    const int t = threadIdx.x, tx = t & 15, ty = t >> 4;
#pragma unroll
    for (int i = 0; i < 4; ++i)
#pragma unroll
        for (int j = 0; j < 4; ++j) {
            const int gi = ti * 64 + ty * 4 + i, gj = tj * 64 + tx * 4 + j;
            g_NS[2][gi * 256 + gj] = acc[i][j] + g_NS[3][gi * 256 + gj];
        }
}

// ---------------- 5) E = scal1*Zn - I (bf16) and b = mu + E mu ----------------
__global__ void bE_kernel() {
    const int c = blockIdx.x, t = threadIdx.x;
    const float sc = g_scal[1];
    float e = sc * g_NS[2][c * 256 + t] - ((c == t) ? 1.0f : 0.0f);
    g_Ebf[c * 256 + t] = __float2bfloat16(e);
    __shared__ float red[256];
    red[t] = e * g_mean[t];
    __syncthreads();
    for (int o = 128; o > 0; o >>= 1) {
        if (t < o) red[t] += red[t + o];
        __syncthreads();
    }
    if (t == 0) g_b[c] = g_mean[c] + red[0];
}

// ---------------- 6) whiten: out = x - b + E @ x  (fp32 X staged once in smem) ----------------
#define PF   132                       // Bf32 pitch in floats (528 B, 16B-aligned, bank-shifted)
#define SZBF (256 * PF * 4)            // 135168
#define WPA  144                       // E chunk pitch (bytes)
#define OE0  SZBF                      // 135168
#define OE1  (SZBF + 256 * WPA)        // 172032
#define WSMEM (SZBF + 2 * 256 * WPA)   // 208896

__global__ __launch_bounds__(512) void whiten_kernel(const float* __restrict__ X,
                                                     float* __restrict__ out) {
    extern __shared__ __align__(128) char sm[];
    const uint32_t sb = smem_u32(sm);
    const float* Bs = (const float*)sm;  // fp32 X tile [k=256][l=128], pitch PF
    const int t = threadIdx.x;
    const int warp = t >> 5, lane = t & 31;
    const int wm = warp >> 2, wn = warp & 3;  // 4x4 warp grid, warp tile 64x32
    const int n = blockIdx.x >> 5, l0 = (blockIdx.x & 31) * 128;
    const uint32_t oB = sb;
    const uint32_t oE[2] = {sb + OE0, sb + OE1};
    const char* Eg = (const char*)g_Ebf;

    auto issueB = [&](int kc) {
#pragma unroll
        for (int i = 0; i < 4; ++i) {
            int slot = t + 512 * i;          // 0..2047
            int row = slot >> 5, seg = slot & 31;
            cpasync16(oB + (uint32_t)(kc * 64 + row) * (PF * 4) + seg * 16,
                      X + (size_t)(n * 256 + kc * 64 + row) * Ldim + l0 + seg * 4);
        }
    };
    auto issueE = [&](int kc) {
#pragma unroll
        for (int i = 0; i < 4; ++i) {
            int slot = t + 512 * i;          // 0..2047
            int row = slot >> 3, seg = slot & 7;
            cpasync16(oE[kc & 1] + (uint32_t)row * WPA + seg * 16,
                      Eg + (size_t)row * 512 + kc * 128 + seg * 16);
        }
    };

    issueB(0); issueE(0); cpcommit();   // G0
    issueB(1); issueE(1); cpcommit();   // G1
    issueB(2); cpcommit();              // G2
    issueB(3); cpcommit();              // G3

    float acc[4][4][4];
#pragma unroll
    for (int i = 0; i < 4; ++i)
#pragma unroll
        for (int j = 0; j < 4; ++j)
#pragma unroll
            for (int r = 0; r < 4; ++r) acc[i][j][r] = 0.0f;

#pragma unroll
    for (int kc = 0; kc < 4; ++kc) {
        if (kc <= 1) cpwait<3>();
        else if (kc == 2) cpwait<1>();
        else cpwait<0>();
        __syncthreads();
        const uint32_t sA = oE[kc & 1];
#pragma unroll
        for (int ks = 0; ks < 4; ++ks) {
            uint32_t af[4][4];
#pragma unroll
            for (int mi = 0; mi < 4; ++mi)
                ldsm4(af[mi], sA + (wm * 64 + mi * 16 + (lane & 15)) * WPA +
                                  ks * 32 + ((lane >> 4) * 16));
            const int krow = kc * 64 + ks * 16 + (lane & 3) * 2;  // k, k+1, k+8, k+9
#pragma unroll
            for (int ni = 0; ni < 4; ++ni) {
                const int ncol = wn * 32 + ni * 8 + (lane >> 2);
                const float f0 = Bs[(size_t)krow * PF + ncol];
                const float f1 = Bs[(size_t)(krow + 1) * PF + ncol];
                const float f2 = Bs[(size_t)(krow + 8) * PF + ncol];
                const float f3 = Bs[(size_t)(krow + 9) * PF + ncol];
                uint32_t bf[2];
                __nv_bfloat162 h0 = __floats2bfloat162_rn(f0, f1);
                __nv_bfloat162 h1 = __floats2bfloat162_rn(f2, f3);
                bf[0] = *(uint32_t*)&h0;
                bf[1] = *(uint32_t*)&h1;
#pragma unroll
                for (int mi = 0; mi < 4; ++mi)
                    mma16816(acc[mi][ni], af[mi], bf);
            }
        }
        __syncthreads();
        if (kc < 2) { issueE(kc + 2); cpcommit(); }  // G4, G5 (buffer freed by sync above)
    }

    // epilogue: out[c][l] = acc + x - b   (x read from smem fp32 tile)
#pragma unroll
    for (int mi = 0; mi < 4; ++mi) {
        const int r0 = wm * 64 + mi * 16 + (lane >> 2);
        const float b0 = g_b[r0], b1 = g_b[r0 + 8];
        float* o0 = out + ((size_t)n * Cdim + r0) * Ldim + l0;
#pragma unroll
        for (int ni = 0; ni < 4; ++ni) {
            const int c = wn * 32 + ni * 8 + (lane & 3) * 2;
            float2 xv0 = *(const float2*)(Bs + (size_t)r0 * PF + c);
            float2 xv1 = *(const float2*)(Bs + (size_t)(r0 + 8) * PF + c);
            float2 ov0, ov1;
            ov0.x = acc[mi][ni][0] + xv0.x - b0;
            ov0.y = acc[mi][ni][1] + xv0.y - b0;
            ov1.x = acc[mi][ni][2] + xv1.x - b1;
            ov1.y = acc[mi][ni][3] + xv1.y - b1;
            *(float2*)(o0 + c) = ov0;
            *(float2*)(o0 + 8 * Ldim + c) = ov1;
        }
    }
}

// ---------------- launch ----------------
extern "C" void kernel_launch(void* const* d_in, const int* in_sizes, int n_in,
                              void* d_out, int out_size) {
    const float* X = (const float*)d_in[0];
    float* out = (float*)d_out;

    cudaFuncSetAttribute(gram_kernel, cudaFuncAttributeMaxDynamicSharedMemorySize, 73728);
    cudaFuncSetAttribute(whiten_kernel, cudaFuncAttributeMaxDynamicSharedMemorySize, WSMEM);

    conv_kernel<<<Nb * Cdim, 256>>>(X);
    mean_reduce<<<1, 256>>>();
    gram_kernel<<<dim3(3, 64, 2), 256, 73728>>>();
    sigma_kernel<<<128, 128>>>();
    trace_kernel<<<1, 256>>>();
    e0_kernel<<<256, 256>>>();
    poly1<<<16, 256>>>();
    poly2<<<16, 256>>>();
    poly3<<<16, 256>>>();
    bE_kernel<<<256, 256>>>();
    whiten_kernel<<<2048, 512, WSMEM>>>(X, out);
}